// round 14
// baseline (speedup 1.0000x reference)
#include <cuda_runtime.h>
#include <cuda_bf16.h>
#include <math.h>
#include <stdint.h>

namespace {

constexpr int kN = 128, kF = 16, kH = 256, kHeads = 4, kFF = 512,
              kOut = 64, kBF = 3, kL = 2, kP = 384, kT = 512, kE = 127,
              kDH = 64, kTN = kT * kN;

// ---- static device scratch (allocation-free) ----
__device__ float g_x[kTN * kH];                     // fp32 residual/LN state
__device__ float g_y[kTN * kH];                     // fp32 pre-LN temp
__device__ __nv_bfloat16 g_xb[kTN * kH];            // bf16 copy of x (GEMM A)
__device__ __nv_bfloat16 g_qkvb[kTN * 3 * kH];      // bf16 qkv
__device__ __nv_bfloat16 g_attnb[kTN * kH];         // bf16 attention out
__device__ __nv_bfloat16 g_ffb[kTN * kFF];          // bf16 ff1 out
__device__ __nv_bfloat16 g_wbf[1048576];            // all weights, bf16
__device__ float g_outpre[kT * kOut];
__device__ float g_WposT[kP * kH];
__device__ int g_parent[kTN];
__device__ int g_slot[kTN];
__device__ int g_maxno[kT];

// weight offsets inside g_wbf (elements)
constexpr int kWOffQkv = 0;
constexpr int kWOffOutp = 393216;
constexpr int kWOffFf1 = 524288;
constexpr int kWOffFf2 = 786432;
constexpr int kWTotal = 1048576;

// ---------------------------------------------------------------------------
// Prep 1: parent/slot for every node.
// ---------------------------------------------------------------------------
__global__ void prep_parent_kernel(const int* __restrict__ adj) {
  int i = blockIdx.x * blockDim.x + threadIdx.x;
  if (i >= kTN) return;
  int local = i & (kN - 1);
  int tree = i >> 7;
  int par = -1, sl = 0;
  if (local != 0) {
    int e = tree * kE + local - 1;
    int p = adj[3 * e], c = adj[3 * e + 1], s = adj[3 * e + 2];
    if (c == i && p >= 0) {
      par = p;
      sl = s;
    }
  }
  g_parent[i] = par;
  g_slot[i] = sl;
}

// ---------------------------------------------------------------------------
// Prep 2: per-tree max(node_order) + W_pos transpose + weight bf16 convert.
// ---------------------------------------------------------------------------
__global__ void prep2_kernel(const int* __restrict__ no,
                             const float* __restrict__ W_pos,
                             const float* __restrict__ qkv_w,
                             const float* __restrict__ outp_w,
                             const float* __restrict__ ff1_w,
                             const float* __restrict__ ff2_w) {
  if (blockIdx.x < kT) {
    __shared__ int red[128];
    int t = blockIdx.x;
    if (threadIdx.x < 128) red[threadIdx.x] = no[t * kN + threadIdx.x];
    __syncthreads();
    for (int s = 64; s > 0; s >>= 1) {
      if (threadIdx.x < s)
        red[threadIdx.x] = max(red[threadIdx.x], red[threadIdx.x + s]);
      __syncthreads();
    }
    if (threadIdx.x == 0) g_maxno[t] = red[0];
  } else if (blockIdx.x < kT + 384) {
    int i = (blockIdx.x - kT) * blockDim.x + threadIdx.x;
    if (i < kP * kH) {
      int p = i / kH, h = i % kH;
      g_WposT[p * kH + h] = W_pos[h * kP + p];
    }
  } else {
    int i = (blockIdx.x - kT - 384) * blockDim.x + threadIdx.x;
    if (i < kWTotal) {
      float v;
      if (i < kWOffOutp) v = qkv_w[i];
      else if (i < kWOffFf1) v = outp_w[i - kWOffOutp];
      else if (i < kWOffFf2) v = ff1_w[i - kWOffFf1];
      else v = ff2_w[i - kWOffFf2];
      g_wbf[i] = __float2bfloat16(v);
    }
  }
}

// ---------------------------------------------------------------------------
// Embedding: writes fp32 x and bf16 xb.
// ---------------------------------------------------------------------------
__global__ void embed_kernel(const float* __restrict__ forest,
                             const int* __restrict__ no,
                             const float* __restrict__ W_in,
                             const float* __restrict__ b_in,
                             const float* __restrict__ b_pos) {
  __shared__ float Wins[kF][kH];
  __shared__ float bib[kH];
  __shared__ float fs[32][kF];
  __shared__ int anc[32][8];
  __shared__ int cnt[32];
  int tid = threadIdx.x;
  int base = blockIdx.x * 32;
#pragma unroll
  for (int j = 0; j < kH * kF / 256; ++j) {
    int idx = tid + j * 256;
    int h = idx / kF, f = idx % kF;
    Wins[f][h] = W_in[idx];
  }
  bib[tid] = b_in[tid] + b_pos[tid];
  {
    int idx = tid;
    if (idx < 32 * kF) {
      int tk = idx / kF, f = idx % kF;
      fs[tk][f] = forest[(size_t)(base + tk) * kF + f];
    }
    idx = tid + 256;
    if (idx < 32 * kF) {
      int tk = idx / kF, f = idx % kF;
      fs[tk][f] = forest[(size_t)(base + tk) * kF + f];
    }
  }
  if (tid < 32) {
    int tok = base + tid;
    int tree = tok / kN;
    int mx = g_maxno[tree];
    int c = tok, n = 0;
    for (int it = 0; it < 8; ++it) {
      int p = g_parent[c];
      if (p < 0) break;
      int pd = mx - no[p];
      int s = g_slot[c] + 1;
      s = s < 0 ? 0 : (s > kBF - 1 ? kBF - 1 : s);
      int idx = pd * kBF + s;
      if (idx >= 0 && idx < kP) anc[tid][n++] = idx;
      c = p;
    }
    cnt[tid] = n;
  }
  __syncthreads();
  int h = tid;
  for (int tk = 0; tk < 32; ++tk) {
    float acc = bib[h];
#pragma unroll
    for (int f = 0; f < kF; ++f) acc += fs[tk][f] * Wins[f][h];
    int c = cnt[tk];
    for (int a = 0; a < c; ++a) acc += g_WposT[anc[tk][a] * kH + h];
    g_x[(size_t)(base + tk) * kH + h] = acc;
    g_xb[(size_t)(base + tk) * kH + h] = __float2bfloat16(acc);
  }
}

// ---------------------------------------------------------------------------
// mma / ldmatrix / cp.async helpers
// ---------------------------------------------------------------------------
enum { EPI_QKV_BF = 0, EPI_RELU_BF = 1, EPI_RES_F32 = 2 };

__device__ __forceinline__ uint32_t pack_bf16(float x, float y) {
  __nv_bfloat162 h = __floats2bfloat162_rn(x, y);
  return *reinterpret_cast<uint32_t*>(&h);
}

__device__ __forceinline__ void mma_bf16(float* c, const uint32_t* a,
                                         const uint32_t* b) {
  asm("mma.sync.aligned.m16n8k16.row.col.f32.bf16.bf16.f32 "
      "{%0,%1,%2,%3},{%4,%5,%6,%7},{%8,%9},{%0,%1,%2,%3};"
      : "+f"(c[0]), "+f"(c[1]), "+f"(c[2]), "+f"(c[3])
      : "r"(a[0]), "r"(a[1]), "r"(a[2]), "r"(a[3]), "r"(b[0]), "r"(b[1]));
}

__device__ __forceinline__ void ldmatrix_x4(uint32_t& r0, uint32_t& r1,
                                            uint32_t& r2, uint32_t& r3,
                                            uint32_t addr) {
  asm volatile(
      "ldmatrix.sync.aligned.m8n8.x4.shared.b16 {%0,%1,%2,%3}, [%4];"
      : "=r"(r0), "=r"(r1), "=r"(r2), "=r"(r3)
      : "r"(addr));
}

__device__ __forceinline__ void cp_async16(uint32_t saddr, const void* gaddr) {
  asm volatile("cp.async.cg.shared.global [%0], [%1], 16;" ::"r"(saddr),
               "l"(gaddr));
}
#define CP_COMMIT asm volatile("cp.async.commit_group;" ::: "memory")
#define CP_WAIT1 asm volatile("cp.async.wait_group 1;" ::: "memory")

// ---------------------------------------------------------------------------
// bf16 GEMM, 3-stage cp.async pipeline, ONE __syncthreads per k-iter.
// Stage layout (dynamic smem): A stages [0,3)*10240 B, B stages at +30720.
// At iter c: wait_group 1 (stage c%3 ready), sync, re-issue into stage
// (c+2)%3 (consumed last iter, safe after this sync), compute stage c%3.
// ---------------------------------------------------------------------------
constexpr int kStageBytes = 10240;                 // 128 rows x 20 u32
constexpr int kGemmDynSmem = 6 * kStageBytes;      // 61440 B

template <int EPI>
__global__ __launch_bounds__(256, 2) void gemm_bf(
    const __nv_bfloat16* __restrict__ A, const __nv_bfloat16* __restrict__ W,
    const float* __restrict__ bias, const float* __restrict__ res,
    float* __restrict__ C, __nv_bfloat16* __restrict__ Cb, int M, int Nd,
    int K) {
  extern __shared__ __align__(16) uint32_t dsm[];
  int tid = threadIdx.x;
  int lane = tid & 31, warp = tid >> 5;
  int g = lane >> 2, tg = lane & 3;
  int wm = (warp & 1) * 64;
  int wn = (warp >> 1) * 32;
  int m0 = blockIdx.y * 128, n0 = blockIdx.x * 128;

  // cp.async mapping: 16B chunk (8 bf16); 2 chunks per matrix per thread.
  int rowA = tid >> 2, qA = tid & 3;
  uint32_t sOffA = (uint32_t)(rowA * 80 + qA * 16);  // +5120 = second half
  uint32_t As0 = (uint32_t)__cvta_generic_to_shared(dsm);
  uint32_t Bs0 = As0 + 3 * kStageBytes;

  float acc[4][4][4];
#pragma unroll
  for (int i = 0; i < 4; ++i)
#pragma unroll
    for (int j = 0; j < 4; ++j)
#pragma unroll
      for (int c = 0; c < 4; ++c) acc[i][j][c] = 0.f;

  auto issue = [&](int s, int kc) {
    const __nv_bfloat16* a1 = A + (size_t)(m0 + rowA) * K + kc * 32 + qA * 8;
    const __nv_bfloat16* w1 = W + (size_t)(n0 + rowA) * K + kc * 32 + qA * 8;
    uint32_t sa = As0 + s * kStageBytes + sOffA;
    uint32_t sb = Bs0 + s * kStageBytes + sOffA;
    cp_async16(sa, a1);
    cp_async16(sa + 5120, a1 + (size_t)64 * K);
    cp_async16(sb, w1);
    cp_async16(sb + 5120, w1 + (size_t)64 * K);
  };

  // ldmatrix lane addressing (stage-0 bases)
  int a_row = wm + (lane & 7) + ((lane >> 3) & 1) * 8;
  int a_col = (lane >> 4) * 4;
  uint32_t a_base = As0 + (uint32_t)((a_row * 20 + a_col) * 4);
  int b_row = wn + (lane & 7) + (lane >> 4) * 8;
  int b_col = ((lane >> 3) & 1) * 4;
  uint32_t b_base = Bs0 + (uint32_t)((b_row * 20 + b_col) * 4);

  const int nk = K >> 5;
  issue(0, 0);
  CP_COMMIT;
  issue(1, 1);
  CP_COMMIT;

  int s = 0;  // stage of iter c (cycles 0,1,2)
  int s2 = 2; // stage of iter c+2
  for (int c = 0; c < nk; ++c) {
    CP_WAIT1;
    __syncthreads();
    if (c + 2 < nk) issue(s2, c + 2);
    CP_COMMIT;
    uint32_t ab = a_base + s * kStageBytes;
    uint32_t bb = b_base + s * kStageBytes;
#pragma unroll
    for (int ks = 0; ks < 2; ++ks) {
      int kb = ks * 8;
      uint32_t af[4][4], bf[4][2];
#pragma unroll
      for (int mi = 0; mi < 4; ++mi) {
        ldmatrix_x4(af[mi][0], af[mi][1], af[mi][2], af[mi][3],
                    ab + (uint32_t)((mi * 16 * 20 + kb) * 4));
      }
#pragma unroll
      for (int p = 0; p < 2; ++p) {
        ldmatrix_x4(bf[p * 2][0], bf[p * 2][1], bf[p * 2 + 1][0],
                    bf[p * 2 + 1][1],
                    bb + (uint32_t)((p * 16 * 20 + kb) * 4));
      }
#pragma unroll
      for (int mi = 0; mi < 4; ++mi)
#pragma unroll
        for (int nj = 0; nj < 4; ++nj) mma_bf16(acc[mi][nj], af[mi], bf[nj]);
    }
    s = (s == 2) ? 0 : s + 1;
    s2 = (s2 == 2) ? 0 : s2 + 1;
  }

  // epilogue
#pragma unroll
  for (int nj = 0; nj < 4; ++nj) {
    int col = n0 + wn + nj * 8 + tg * 2;
    float b0 = bias[col], b1 = bias[col + 1];
#pragma unroll
    for (int mi = 0; mi < 4; ++mi) {
      int row = m0 + wm + mi * 16 + g;
      float v00 = acc[mi][nj][0] + b0;
      float v01 = acc[mi][nj][1] + b1;
      float v10 = acc[mi][nj][2] + b0;
      float v11 = acc[mi][nj][3] + b1;
      if (EPI == EPI_RELU_BF) {
        v00 = fmaxf(v00, 0.f);
        v01 = fmaxf(v01, 0.f);
        v10 = fmaxf(v10, 0.f);
        v11 = fmaxf(v11, 0.f);
      }
      if (EPI == EPI_RES_F32) {
        float2 r0 = *(const float2*)(res + (size_t)row * Nd + col);
        float2 r1 = *(const float2*)(res + (size_t)(row + 8) * Nd + col);
        v00 += r0.x;
        v01 += r0.y;
        v10 += r1.x;
        v11 += r1.y;
        float2 o0 = {v00, v01}, o1 = {v10, v11};
        *(float2*)(C + (size_t)row * Nd + col) = o0;
        *(float2*)(C + (size_t)(row + 8) * Nd + col) = o1;
      } else {
        *(uint32_t*)(Cb + (size_t)row * Nd + col) = pack_bf16(v00, v01);
        *(uint32_t*)(Cb + (size_t)(row + 8) * Nd + col) = pack_bf16(v10, v11);
      }
    }
  }
}

// ---------------------------------------------------------------------------
// bf16 tensor-core attention (unchanged from R12).
// ---------------------------------------------------------------------------
constexpr int kQStr = 36;
constexpr int kVStr = 68;
constexpr int kAttnSmem = (2 * 128 * kQStr + 64 * kVStr) * 4;  // 54272

__global__ __launch_bounds__(256, 2) void attn_tc(
    const __nv_bfloat16* __restrict__ qkv, __nv_bfloat16* __restrict__ out) {
  extern __shared__ uint32_t sm[];
  uint32_t* Qs = sm;
  uint32_t* Ks = sm + 128 * kQStr;
  uint32_t* Vt = sm + 2 * 128 * kQStr;
  int t = blockIdx.x >> 2, h = blockIdx.x & 3;
  int tid = threadIdx.x, lane = tid & 31, warp = tid >> 5;
  int g = lane >> 2, tg = lane & 3;
  const size_t base = (size_t)t * kN * (3 * kH);

  {
    int row = tid >> 1, part = tid & 1;
    const uint32_t* qp =
        (const uint32_t*)(qkv + base + (size_t)row * (3 * kH) + h * kDH) +
        part * 16;
    const uint32_t* kp = qp + kH / 2;
    uint32_t* qd = Qs + row * kQStr + part * 16;
    uint32_t* kd = Ks + row * kQStr + part * 16;
#pragma unroll
    for (int i = 0; i < 4; ++i) {
      ((uint4*)qd)[i] = ((const uint4*)qp)[i];
      ((uint4*)kd)[i] = ((const uint4*)kp)[i];
    }
    const uint4* vp = (const uint4*)(qkv + base + (size_t)row * (3 * kH) +
                                     2 * kH + h * kDH + part * 32);
    __nv_bfloat16* vtb = (__nv_bfloat16*)Vt;
#pragma unroll
    for (int j = 0; j < 4; ++j) {
      uint4 v = vp[j];
      int d = part * 32 + j * 8;
      __nv_bfloat162 p0 = *(__nv_bfloat162*)&v.x;
      __nv_bfloat162 p1 = *(__nv_bfloat162*)&v.y;
      __nv_bfloat162 p2 = *(__nv_bfloat162*)&v.z;
      __nv_bfloat162 p3 = *(__nv_bfloat162*)&v.w;
      vtb[(d + 0) * (2 * kVStr) + row] = p0.x;
      vtb[(d + 1) * (2 * kVStr) + row] = p0.y;
      vtb[(d + 2) * (2 * kVStr) + row] = p1.x;
      vtb[(d + 3) * (2 * kVStr) + row] = p1.y;
      vtb[(d + 4) * (2 * kVStr) + row] = p2.x;
      vtb[(d + 5) * (2 * kVStr) + row] = p2.y;
      vtb[(d + 6) * (2 * kVStr) + row] = p3.x;
      vtb[(d + 7) * (2 * kVStr) + row] = p3.y;
    }
  }
  __syncthreads();

  float sacc[16][4];
#pragma unroll
  for (int nj = 0; nj < 16; ++nj)
#pragma unroll
    for (int c = 0; c < 4; ++c) sacc[nj][c] = 0.f;

  uint32_t a_base = (uint32_t)__cvta_generic_to_shared(
      Qs + (warp * 16 + (lane & 7) + ((lane >> 3) & 1) * 8) * kQStr +
      (lane >> 4) * 4);
  uint32_t k_base = (uint32_t)__cvta_generic_to_shared(
      Ks + ((lane & 7) + (lane >> 4) * 8) * kQStr + ((lane >> 3) & 1) * 4);

#pragma unroll
  for (int ks = 0; ks < 4; ++ks) {
    int kb = ks * 8;
    uint32_t af[4], bf[16][2];
    ldmatrix_x4(af[0], af[1], af[2], af[3], a_base + (uint32_t)(kb * 4));
#pragma unroll
    for (int p = 0; p < 8; ++p) {
      ldmatrix_x4(bf[p * 2][0], bf[p * 2][1], bf[p * 2 + 1][0],
                  bf[p * 2 + 1][1],
                  k_base + (uint32_t)((p * 16 * kQStr + kb) * 4));
    }
#pragma unroll
    for (int nj = 0; nj < 16; ++nj) mma_bf16(sacc[nj], af, bf[nj]);
  }

  const float scale = 0.125f;
  float mx0 = -1e30f, mx1 = -1e30f;
#pragma unroll
  for (int nj = 0; nj < 16; ++nj) {
    mx0 = fmaxf(mx0, fmaxf(sacc[nj][0], sacc[nj][1]));
    mx1 = fmaxf(mx1, fmaxf(sacc[nj][2], sacc[nj][3]));
  }
  mx0 = fmaxf(mx0, __shfl_xor_sync(~0u, mx0, 1));
  mx0 = fmaxf(mx0, __shfl_xor_sync(~0u, mx0, 2));
  mx1 = fmaxf(mx1, __shfl_xor_sync(~0u, mx1, 1));
  mx1 = fmaxf(mx1, __shfl_xor_sync(~0u, mx1, 2));
  mx0 *= scale;
  mx1 *= scale;
  float sum0 = 0.f, sum1 = 0.f;
#pragma unroll
  for (int nj = 0; nj < 16; ++nj) {
    sacc[nj][0] = __expf(sacc[nj][0] * scale - mx0);
    sacc[nj][1] = __expf(sacc[nj][1] * scale - mx0);
    sacc[nj][2] = __expf(sacc[nj][2] * scale - mx1);
    sacc[nj][3] = __expf(sacc[nj][3] * scale - mx1);
    sum0 += sacc[nj][0] + sacc[nj][1];
    sum1 += sacc[nj][2] + sacc[nj][3];
  }
  sum0 += __shfl_xor_sync(~0u, sum0, 1);
  sum0 += __shfl_xor_sync(~0u, sum0, 2);
  sum1 += __shfl_xor_sync(~0u, sum1, 1);
  sum1 += __shfl_xor_sync(~0u, sum1, 2);
  float inv0 = 1.f / sum0, inv1 = 1.f / sum1;

  uint32_t pfrag[8][4];
#pragma unroll
  for (int ks = 0; ks < 8; ++ks) {
    pfrag[ks][0] = pack_bf16(sacc[2 * ks][0] * inv0, sacc[2 * ks][1] * inv0);
    pfrag[ks][1] = pack_bf16(sacc[2 * ks][2] * inv1, sacc[2 * ks][3] * inv1);
    pfrag[ks][2] =
        pack_bf16(sacc[2 * ks + 1][0] * inv0, sacc[2 * ks + 1][1] * inv0);
    pfrag[ks][3] =
        pack_bf16(sacc[2 * ks + 1][2] * inv1, sacc[2 * ks + 1][3] * inv1);
  }

  float oacc[8][4];
#pragma unroll
  for (int nj = 0; nj < 8; ++nj)
#pragma unroll
    for (int c = 0; c < 4; ++c) oacc[nj][c] = 0.f;

  uint32_t v_base = (uint32_t)__cvta_generic_to_shared(
      Vt + ((lane & 7) + (lane >> 4) * 8) * kVStr + ((lane >> 3) & 1) * 4);
#pragma unroll
  for (int ks = 0; ks < 8; ++ks) {
    int kb = ks * 8;
    uint32_t bf[8][2];
#pragma unroll
    for (int p = 0; p < 4; ++p) {
      ldmatrix_x4(bf[p * 2][0], bf[p * 2][1], bf[p * 2 + 1][0],
                  bf[p * 2 + 1][1],
                  v_base + (uint32_t)((p * 16 * kVStr + kb) * 4));
    }
#pragma unroll
    for (int nj = 0; nj < 8; ++nj) mma_bf16(oacc[nj], pfrag[ks], bf[nj]);
  }

  int r0 = warp * 16 + g, r1 = r0 + 8;
  __nv_bfloat16* op = out + (size_t)(t * kN) * kH + h * kDH;
#pragma unroll
  for (int nj = 0; nj < 8; ++nj) {
    int col = nj * 8 + tg * 2;
    *(uint32_t*)(op + (size_t)r0 * kH + col) =
        pack_bf16(oacc[nj][0], oacc[nj][1]);
    *(uint32_t*)(op + (size_t)r1 * kH + col) =
        pack_bf16(oacc[nj][2], oacc[nj][3]);
  }
}

// ---------------------------------------------------------------------------
// LayerNorm: warp per token; writes fp32 x and bf16 xb.
// ---------------------------------------------------------------------------
__global__ __launch_bounds__(256) void ln_kernel(
    const float* __restrict__ y, const float* __restrict__ w,
    const float* __restrict__ b, float* __restrict__ x,
    __nv_bfloat16* __restrict__ xb) {
  int warp = threadIdx.x >> 5, lane = threadIdx.x & 31;
  size_t tok = (size_t)blockIdx.x * 8 + warp;
  const float* yp = y + tok * kH;
  float4 a = *(const float4*)(yp + lane * 4);
  float4 c = *(const float4*)(yp + 128 + lane * 4);
  float sum = a.x + a.y + a.z + a.w + c.x + c.y + c.z + c.w;
#pragma unroll
  for (int s = 16; s; s >>= 1) sum += __shfl_xor_sync(~0u, sum, s);
  float mu = sum * (1.f / kH);
  float d0 = a.x - mu, d1 = a.y - mu, d2 = a.z - mu, d3 = a.w - mu;
  float d4 = c.x - mu, d5 = c.y - mu, d6 = c.z - mu, d7 = c.w - mu;
  float sq = d0 * d0 + d1 * d1 + d2 * d2 + d3 * d3 + d4 * d4 + d5 * d5 +
             d6 * d6 + d7 * d7;
#pragma unroll
  for (int s = 16; s; s >>= 1) sq += __shfl_xor_sync(~0u, sq, s);
  float inv = rsqrtf(sq * (1.f / kH) + 1e-5f);
  float4 w0 = *(const float4*)(w + lane * 4);
  float4 w1 = *(const float4*)(w + 128 + lane * 4);
  float4 b0 = *(const float4*)(b + lane * 4);
  float4 b1 = *(const float4*)(b + 128 + lane * 4);
  float* xp = x + tok * kH;
  float4 o0 = {d0 * inv * w0.x + b0.x, d1 * inv * w0.y + b0.y,
               d2 * inv * w0.z + b0.z, d3 * inv * w0.w + b0.w};
  float4 o1 = {d4 * inv * w1.x + b1.x, d5 * inv * w1.y + b1.y,
               d6 * inv * w1.z + b1.z, d7 * inv * w1.w + b1.w};
  *(float4*)(xp + lane * 4) = o0;
  *(float4*)(xp + 128 + lane * 4) = o1;
  uint2 p0 = {pack_bf16(o0.x, o0.y), pack_bf16(o0.z, o0.w)};
  uint2 p1 = {pack_bf16(o1.x, o1.y), pack_bf16(o1.z, o1.w)};
  *(uint2*)(xb + tok * kH + lane * 4) = p0;
  *(uint2*)(xb + tok * kH + 128 + lane * 4) = p1;
}

// ---------------------------------------------------------------------------
// Output GEMM: out_pre[512,64] = x[512, 32768] @ W_out[64,32768]^T, split-K
// ---------------------------------------------------------------------------
constexpr int kKTotal = kN * kH;
constexpr int kKSplit = 16;
constexpr int kKChunk = kKTotal / kKSplit;

__global__ void zero_outpre() {
  int i = blockIdx.x * blockDim.x + threadIdx.x;
  if (i < kT * kOut) g_outpre[i] = 0.f;
}

__global__ void gemm_out_kernel(const float* __restrict__ Afull,
                                const float* __restrict__ Wout) {
  __shared__ float As[16][68];
  __shared__ float Bs[16][68];
  int m0 = blockIdx.y * 64;
  int kc0 = blockIdx.x * kKChunk;
  int tid = threadIdx.x;
  int tx = tid & 15, ty = tid >> 4;
  int lm = tid >> 2, lk = (tid & 3) * 4;
  float acc[4][4] = {};
  const float* Aptr = Afull + (size_t)(m0 + lm) * kKTotal + kc0 + lk;
  const float* Wptr = Wout + (size_t)lm * kKTotal + kc0 + lk;
  for (int k0 = 0; k0 < kKChunk; k0 += 16) {
    float4 av = *(const float4*)(Aptr + k0);
    float4 wv = *(const float4*)(Wptr + k0);
    As[lk + 0][lm] = av.x;
    As[lk + 1][lm] = av.y;
    As[lk + 2][lm] = av.z;
    As[lk + 3][lm] = av.w;
    Bs[lk + 0][lm] = wv.x;
    Bs[lk + 1][lm] = wv.y;
    Bs[lk + 2][lm] = wv.z;
    Bs[lk + 3][lm] = wv.w;
    __syncthreads();
#pragma unroll
    for (int k = 0; k < 16; ++k) {
      float4 a4 = *(const float4*)&As[k][ty * 4];
      float4 b4 = *(const float4*)&Bs[k][tx * 4];
      float a[4] = {a4.x, a4.y, a4.z, a4.w};
      float b[4] = {b4.x, b4.y, b4.z, b4.w};
#pragma unroll
      for (int i = 0; i < 4; ++i)
#pragma unroll
        for (int j = 0; j < 4; ++j) acc[i][j] += a[i] * b[j];
    }
    __syncthreads();
  }
#pragma unroll
  for (int i = 0; i < 4; ++i)
#pragma unroll
    for (int j = 0; j < 4; ++j)
      atomicAdd(&g_outpre[(m0 + ty * 4 + i) * kOut + tx * 4 + j], acc[i][j]);
}

__global__ void lnf_kernel(const float* __restrict__ b_out,
                           const float* __restrict__ w,
                           const float* __restrict__ bb,
                           float* __restrict__ out) {
  __shared__ float red[64];
  int t = blockIdx.x, o = threadIdx.x;
  float v = g_outpre[t * kOut + o] + b_out[o];
  red[o] = v;
  __syncthreads();
  for (int s = 32; s > 0; s >>= 1) {
    if (o < s) red[o] += red[o + s];
    __syncthreads();
  }
  float mu = red[0] * (1.f / kOut);
  __syncthreads();
  float d = v - mu;
  red[o] = d * d;
  __syncthreads();
  for (int s = 32; s > 0; s >>= 1) {
    if (o < s) red[o] += red[o + s];
    __syncthreads();
  }
  float var = red[0] * (1.f / kOut);
  out[t * kOut + o] = d * rsqrtf(var + 1e-5f) * w[o] + bb[o];
}

}  // namespace

extern "C" void kernel_launch(void* const* d_in, const int* in_sizes, int n_in,
                              void* d_out, int out_size) {
  const float* forest = (const float*)d_in[0];
  const int* adj = (const int*)d_in[1];
  const int* no = (const int*)d_in[2];
  const float* W_in = (const float*)d_in[3];
  const float* b_in = (const float*)d_in[4];
  const float* W_pos = (const float*)d_in[5];
  const float* b_pos = (const float*)d_in[6];
  const float* qkv_w = (const float*)d_in[7];
  const float* qkv_b = (const float*)d_in[8];
  const float* outp_w = (const float*)d_in[9];
  const float* outp_b = (const float*)d_in[10];
  const float* ln1_w = (const float*)d_in[11];
  const float* ln1_b = (const float*)d_in[12];
  const float* ff1_w = (const float*)d_in[13];
  const float* ff1_b = (const float*)d_in[14];
  const float* ff2_w = (const float*)d_in[15];
  const float* ff2_b = (const float*)d_in[16];
  const float* ln2_w = (const float*)d_in[17];
  const float* ln2_b = (const float*)d_in[18];
  const float* W_out = (const float*)d_in[19];
  const float* b_out = (const float*)d_in[20];
  const float* lnf_w = (const float*)d_in[21];
  const float* lnf_b = (const float*)d_in[22];
  float* out = (float*)d_out;

  float *px, *py;
  __nv_bfloat16 *pxb, *pqkvb, *pattnb, *pffb, *pwbf;
  cudaGetSymbolAddress((void**)&px, g_x);
  cudaGetSymbolAddress((void**)&py, g_y);
  cudaGetSymbolAddress((void**)&pxb, g_xb);
  cudaGetSymbolAddress((void**)&pqkvb, g_qkvb);
  cudaGetSymbolAddress((void**)&pattnb, g_attnb);
  cudaGetSymbolAddress((void**)&pffb, g_ffb);
  cudaGetSymbolAddress((void**)&pwbf, g_wbf);

  cudaFuncSetAttribute(attn_tc, cudaFuncAttributeMaxDynamicSharedMemorySize,
                       kAttnSmem);
  cudaFuncSetAttribute(gemm_bf<EPI_QKV_BF>,
                       cudaFuncAttributeMaxDynamicSharedMemorySize,
                       kGemmDynSmem);
  cudaFuncSetAttribute(gemm_bf<EPI_RELU_BF>,
                       cudaFuncAttributeMaxDynamicSharedMemorySize,
                       kGemmDynSmem);
  cudaFuncSetAttribute(gemm_bf<EPI_RES_F32>,
                       cudaFuncAttributeMaxDynamicSharedMemorySize,
                       kGemmDynSmem);

  // launch 0
  prep_parent_kernel<<<(kTN + 255) / 256, 256>>>(adj);
  // launch 1 (maxno + wpos transpose + weight bf16 conversion)
  prep2_kernel<<<kT + 384 + kWTotal / 256, 256>>>(no, W_pos, qkv_w, outp_w,
                                                  ff1_w, ff2_w);
  // launch 2
  embed_kernel<<<kTN / 32, 256>>>(forest, no, W_in, b_in, b_pos);

  dim3 blk(256);
  for (int l = 0; l < kL; ++l) {
    // launch 3 on l==0: ncu profiles this (qkv GEMM).
    gemm_bf<EPI_QKV_BF>
        <<<dim3((3 * kH) / 128, kTN / 128), blk, kGemmDynSmem>>>(
            pxb, pwbf + kWOffQkv + (size_t)l * 3 * kH * kH,
            qkv_b + (size_t)l * 3 * kH, nullptr, nullptr, pqkvb, kTN, 3 * kH,
            kH);
    attn_tc<<<kT * kHeads, 256, kAttnSmem>>>(pqkvb, pattnb);
    gemm_bf<EPI_RES_F32><<<dim3(kH / 128, kTN / 128), blk, kGemmDynSmem>>>(
        pattnb, pwbf + kWOffOutp + (size_t)l * kH * kH,
        outp_b + (size_t)l * kH, px, py, nullptr, kTN, kH, kH);
    ln_kernel<<<kTN / 8, 256>>>(py, ln1_w + (size_t)l * kH,
                                ln1_b + (size_t)l * kH, px, pxb);
    gemm_bf<EPI_RELU_BF><<<dim3(kFF / 128, kTN / 128), blk, kGemmDynSmem>>>(
        pxb, pwbf + kWOffFf1 + (size_t)l * kFF * kH, ff1_b + (size_t)l * kFF,
        nullptr, nullptr, pffb, kTN, kFF, kH);
    gemm_bf<EPI_RES_F32><<<dim3(kH / 128, kTN / 128), blk, kGemmDynSmem>>>(
        pffb, pwbf + kWOffFf2 + (size_t)l * kH * kFF, ff2_b + (size_t)l * kH,
        px, py, nullptr, kTN, kH, kFF);
    ln_kernel<<<kTN / 8, 256>>>(py, ln2_w + (size_t)l * kH,
                                ln2_b + (size_t)l * kH, px, pxb);
  }

  zero_outpre<<<(kT * kOut + 255) / 256, 256>>>();
  gemm_out_kernel<<<dim3(kKSplit, kT / 64), blk>>>(px, W_out);
  lnf_kernel<<<kT, kOut>>>(b_out, lnf_w, lnf_b, out);
}

// round 15
// speedup vs baseline: 1.4842x; 1.4842x over previous
#include <cuda_runtime.h>
#include <cuda_bf16.h>
#include <math.h>
#include <stdint.h>

namespace {

constexpr int kN = 128, kF = 16, kH = 256, kHeads = 4, kFF = 512,
              kOut = 64, kBF = 3, kL = 2, kP = 384, kT = 512, kE = 127,
              kDH = 64, kTN = kT * kN;

// ---- static device scratch (allocation-free) ----
__device__ float g_x[kTN * kH];                     // fp32 residual/LN state
__device__ float g_y[kTN * kH];                     // fp32 pre-LN temp
__device__ __nv_bfloat16 g_xb[kTN * kH];            // bf16 copy of x (GEMM A)
__device__ __nv_bfloat16 g_qkvb[kTN * 3 * kH];      // bf16 qkv
__device__ __nv_bfloat16 g_attnb[kTN * kH];         // bf16 attention out
__device__ __nv_bfloat16 g_ffb[kTN * kFF];          // bf16 ff1 out
__device__ __nv_bfloat16 g_wbf[1048576];            // all weights, bf16
__device__ float g_outpre[kT * kOut];
__device__ float g_WposT[kP * kH];
__device__ int g_parent[kTN];
__device__ int g_slot[kTN];
__device__ int g_maxno[kT];

constexpr int kWOffQkv = 0;
constexpr int kWOffOutp = 393216;
constexpr int kWOffFf1 = 524288;
constexpr int kWOffFf2 = 786432;
constexpr int kWTotal = 1048576;

// ---------------------------------------------------------------------------
// Prep 1: parent/slot for every node.
// ---------------------------------------------------------------------------
__global__ void prep_parent_kernel(const int* __restrict__ adj) {
  int i = blockIdx.x * blockDim.x + threadIdx.x;
  if (i >= kTN) return;
  int local = i & (kN - 1);
  int tree = i >> 7;
  int par = -1, sl = 0;
  if (local != 0) {
    int e = tree * kE + local - 1;
    int p = adj[3 * e], c = adj[3 * e + 1], s = adj[3 * e + 2];
    if (c == i && p >= 0) {
      par = p;
      sl = s;
    }
  }
  g_parent[i] = par;
  g_slot[i] = sl;
}

// ---------------------------------------------------------------------------
// Prep 2: per-tree max(node_order) + W_pos transpose + weight bf16 convert.
// ---------------------------------------------------------------------------
__global__ void prep2_kernel(const int* __restrict__ no,
                             const float* __restrict__ W_pos,
                             const float* __restrict__ qkv_w,
                             const float* __restrict__ outp_w,
                             const float* __restrict__ ff1_w,
                             const float* __restrict__ ff2_w) {
  if (blockIdx.x < kT) {
    __shared__ int red[128];
    int t = blockIdx.x;
    if (threadIdx.x < 128) red[threadIdx.x] = no[t * kN + threadIdx.x];
    __syncthreads();
    for (int s = 64; s > 0; s >>= 1) {
      if (threadIdx.x < s)
        red[threadIdx.x] = max(red[threadIdx.x], red[threadIdx.x + s]);
      __syncthreads();
    }
    if (threadIdx.x == 0) g_maxno[t] = red[0];
  } else if (blockIdx.x < kT + 384) {
    int i = (blockIdx.x - kT) * blockDim.x + threadIdx.x;
    if (i < kP * kH) {
      int p = i / kH, h = i % kH;
      g_WposT[p * kH + h] = W_pos[h * kP + p];
    }
  } else {
    int i = (blockIdx.x - kT - 384) * blockDim.x + threadIdx.x;
    if (i < kWTotal) {
      float v;
      if (i < kWOffOutp) v = qkv_w[i];
      else if (i < kWOffFf1) v = outp_w[i - kWOffOutp];
      else if (i < kWOffFf2) v = ff1_w[i - kWOffFf1];
      else v = ff2_w[i - kWOffFf2];
      g_wbf[i] = __float2bfloat16(v);
    }
  }
}

// ---------------------------------------------------------------------------
// Embedding: writes fp32 x and bf16 xb.
// ---------------------------------------------------------------------------
__global__ void embed_kernel(const float* __restrict__ forest,
                             const int* __restrict__ no,
                             const float* __restrict__ W_in,
                             const float* __restrict__ b_in,
                             const float* __restrict__ b_pos) {
  __shared__ float Wins[kF][kH];
  __shared__ float bib[kH];
  __shared__ float fs[32][kF];
  __shared__ int anc[32][8];
  __shared__ int cnt[32];
  int tid = threadIdx.x;
  int base = blockIdx.x * 32;
#pragma unroll
  for (int j = 0; j < kH * kF / 256; ++j) {
    int idx = tid + j * 256;
    int h = idx / kF, f = idx % kF;
    Wins[f][h] = W_in[idx];
  }
  bib[tid] = b_in[tid] + b_pos[tid];
  {
    int idx = tid;
    if (idx < 32 * kF) {
      int tk = idx / kF, f = idx % kF;
      fs[tk][f] = forest[(size_t)(base + tk) * kF + f];
    }
    idx = tid + 256;
    if (idx < 32 * kF) {
      int tk = idx / kF, f = idx % kF;
      fs[tk][f] = forest[(size_t)(base + tk) * kF + f];
    }
  }
  if (tid < 32) {
    int tok = base + tid;
    int tree = tok / kN;
    int mx = g_maxno[tree];
    int c = tok, n = 0;
    for (int it = 0; it < 8; ++it) {
      int p = g_parent[c];
      if (p < 0) break;
      int pd = mx - no[p];
      int s = g_slot[c] + 1;
      s = s < 0 ? 0 : (s > kBF - 1 ? kBF - 1 : s);
      int idx = pd * kBF + s;
      if (idx >= 0 && idx < kP) anc[tid][n++] = idx;
      c = p;
    }
    cnt[tid] = n;
  }
  __syncthreads();
  int h = tid;
  for (int tk = 0; tk < 32; ++tk) {
    float acc = bib[h];
#pragma unroll
    for (int f = 0; f < kF; ++f) acc += fs[tk][f] * Wins[f][h];
    int c = cnt[tk];
    for (int a = 0; a < c; ++a) acc += g_WposT[anc[tk][a] * kH + h];
    g_x[(size_t)(base + tk) * kH + h] = acc;
    g_xb[(size_t)(base + tk) * kH + h] = __float2bfloat16(acc);
  }
}

// ---------------------------------------------------------------------------
// mma / ldmatrix / cp.async helpers
// ---------------------------------------------------------------------------
enum { EPI_QKV_BF = 0, EPI_RELU_BF = 1, EPI_RES_F32 = 2 };

__device__ __forceinline__ uint32_t pack_bf16(float x, float y) {
  __nv_bfloat162 h = __floats2bfloat162_rn(x, y);
  return *reinterpret_cast<uint32_t*>(&h);
}

__device__ __forceinline__ void mma_bf16(float* c, const uint32_t* a,
                                         const uint32_t* b) {
  asm("mma.sync.aligned.m16n8k16.row.col.f32.bf16.bf16.f32 "
      "{%0,%1,%2,%3},{%4,%5,%6,%7},{%8,%9},{%0,%1,%2,%3};"
      : "+f"(c[0]), "+f"(c[1]), "+f"(c[2]), "+f"(c[3])
      : "r"(a[0]), "r"(a[1]), "r"(a[2]), "r"(a[3]), "r"(b[0]), "r"(b[1]));
}

__device__ __forceinline__ void ldmatrix_x4(uint32_t& r0, uint32_t& r1,
                                            uint32_t& r2, uint32_t& r3,
                                            uint32_t addr) {
  asm volatile(
      "ldmatrix.sync.aligned.m8n8.x4.shared.b16 {%0,%1,%2,%3}, [%4];"
      : "=r"(r0), "=r"(r1), "=r"(r2), "=r"(r3)
      : "r"(addr));
}

__device__ __forceinline__ void cp_async16(uint32_t saddr, const void* gaddr) {
  asm volatile("cp.async.cg.shared.global [%0], [%1], 16;" ::"r"(saddr),
               "l"(gaddr));
}
#define CP_COMMIT asm volatile("cp.async.commit_group;" ::: "memory")
#define CP_WAIT1 asm volatile("cp.async.wait_group 1;" ::: "memory")

// ---------------------------------------------------------------------------
// bf16 GEMM: R12 structure (2 stages, two syncs/iter, issue AFTER compute),
// K-tile widened 32 -> 64 (4 k-steps/iter). Row stride 36 u32 (144 B,
// 16B-aligned, conflict-free ldmatrix — same layout as attention Qs).
// Dynamic smem: A stages [0,2)*18432, B stages at +36864. Total 73728 B.
// ---------------------------------------------------------------------------
constexpr int kGRowU32 = 36;
constexpr int kGStage = 128 * kGRowU32 * 4;        // 18432 B
constexpr int kGemmDynSmem = 4 * kGStage;          // 73728 B

template <int EPI>
__global__ __launch_bounds__(256, 2) void gemm_bf(
    const __nv_bfloat16* __restrict__ A, const __nv_bfloat16* __restrict__ W,
    const float* __restrict__ bias, const float* __restrict__ res,
    float* __restrict__ C, __nv_bfloat16* __restrict__ Cb, int M, int Nd,
    int K) {
  extern __shared__ __align__(16) uint32_t dsm[];
  int tid = threadIdx.x;
  int lane = tid & 31, warp = tid >> 5;
  int g = lane >> 2, tg = lane & 3;
  int wm = (warp & 1) * 64;
  int wn = (warp >> 1) * 32;
  int m0 = blockIdx.y * 128, n0 = blockIdx.x * 128;

  uint32_t As0 = (uint32_t)__cvta_generic_to_shared(dsm);
  uint32_t Bs0 = As0 + 2 * kGStage;

  float acc[4][4][4];
#pragma unroll
  for (int i = 0; i < 4; ++i)
#pragma unroll
    for (int j = 0; j < 4; ++j)
#pragma unroll
      for (int c = 0; c < 4; ++c) acc[i][j][c] = 0.f;

  // cp.async: 128x64 bf16 tile = 1024 x 16B chunks; 4 chunks/thread/matrix.
  auto issue = [&](int s, int kc) {
    uint32_t sa = As0 + s * kGStage;
    uint32_t sb = Bs0 + s * kGStage;
#pragma unroll
    for (int p = 0; p < 4; ++p) {
      int ci = tid + 256 * p;
      int row = ci >> 3, cq = ci & 7;
      uint32_t so = (uint32_t)(row * 144 + cq * 16);
      cp_async16(sa + so, A + (size_t)(m0 + row) * K + kc * 64 + cq * 8);
      cp_async16(sb + so, W + (size_t)(n0 + row) * K + kc * 64 + cq * 8);
    }
  };

  // ldmatrix lane addressing (stage-0 bases)
  int a_row = wm + (lane & 7) + ((lane >> 3) & 1) * 8;
  int a_col = (lane >> 4) * 4;
  uint32_t a_base = As0 + (uint32_t)((a_row * kGRowU32 + a_col) * 4);
  int b_row = wn + (lane & 7) + (lane >> 4) * 8;
  int b_col = ((lane >> 3) & 1) * 4;
  uint32_t b_base = Bs0 + (uint32_t)((b_row * kGRowU32 + b_col) * 4);

  const int nk = K >> 6;
  issue(0, 0);
  CP_COMMIT;
  issue(1, 1);
  CP_COMMIT;

  for (int c = 0; c < nk; ++c) {
    int b = c & 1;
    CP_WAIT1;
    __syncthreads();
    uint32_t ab = a_base + b * kGStage;
    uint32_t bb = b_base + b * kGStage;
#pragma unroll
    for (int ks = 0; ks < 4; ++ks) {
      int kb = ks * 8;
      uint32_t af[4][4], bf[4][2];
#pragma unroll
      for (int mi = 0; mi < 4; ++mi) {
        ldmatrix_x4(af[mi][0], af[mi][1], af[mi][2], af[mi][3],
                    ab + (uint32_t)((mi * 16 * kGRowU32 + kb) * 4));
      }
#pragma unroll
      for (int p = 0; p < 2; ++p) {
        ldmatrix_x4(bf[p * 2][0], bf[p * 2][1], bf[p * 2 + 1][0],
                    bf[p * 2 + 1][1],
                    bb + (uint32_t)((p * 16 * kGRowU32 + kb) * 4));
      }
#pragma unroll
      for (int mi = 0; mi < 4; ++mi)
#pragma unroll
        for (int nj = 0; nj < 4; ++nj) mma_bf16(acc[mi][nj], af[mi], bf[nj]);
    }
    __syncthreads();
    if (c + 2 < nk) issue(b, c + 2);
    CP_COMMIT;
  }

  // epilogue
#pragma unroll
  for (int nj = 0; nj < 4; ++nj) {
    int col = n0 + wn + nj * 8 + tg * 2;
    float b0 = bias[col], b1 = bias[col + 1];
#pragma unroll
    for (int mi = 0; mi < 4; ++mi) {
      int row = m0 + wm + mi * 16 + g;
      float v00 = acc[mi][nj][0] + b0;
      float v01 = acc[mi][nj][1] + b1;
      float v10 = acc[mi][nj][2] + b0;
      float v11 = acc[mi][nj][3] + b1;
      if (EPI == EPI_RELU_BF) {
        v00 = fmaxf(v00, 0.f);
        v01 = fmaxf(v01, 0.f);
        v10 = fmaxf(v10, 0.f);
        v11 = fmaxf(v11, 0.f);
      }
      if (EPI == EPI_RES_F32) {
        float2 r0 = *(const float2*)(res + (size_t)row * Nd + col);
        float2 r1 = *(const float2*)(res + (size_t)(row + 8) * Nd + col);
        v00 += r0.x;
        v01 += r0.y;
        v10 += r1.x;
        v11 += r1.y;
        float2 o0 = {v00, v01}, o1 = {v10, v11};
        *(float2*)(C + (size_t)row * Nd + col) = o0;
        *(float2*)(C + (size_t)(row + 8) * Nd + col) = o1;
      } else {
        *(uint32_t*)(Cb + (size_t)row * Nd + col) = pack_bf16(v00, v01);
        *(uint32_t*)(Cb + (size_t)(row + 8) * Nd + col) = pack_bf16(v10, v11);
      }
    }
  }
}

// ---------------------------------------------------------------------------
// bf16 tensor-core attention (unchanged from R12).
// ---------------------------------------------------------------------------
constexpr int kQStr = 36;
constexpr int kVStr = 68;
constexpr int kAttnSmem = (2 * 128 * kQStr + 64 * kVStr) * 4;  // 54272

__global__ __launch_bounds__(256, 2) void attn_tc(
    const __nv_bfloat16* __restrict__ qkv, __nv_bfloat16* __restrict__ out) {
  extern __shared__ uint32_t sm[];
  uint32_t* Qs = sm;
  uint32_t* Ks = sm + 128 * kQStr;
  uint32_t* Vt = sm + 2 * 128 * kQStr;
  int t = blockIdx.x >> 2, h = blockIdx.x & 3;
  int tid = threadIdx.x, lane = tid & 31, warp = tid >> 5;
  int g = lane >> 2, tg = lane & 3;
  const size_t base = (size_t)t * kN * (3 * kH);

  {
    int row = tid >> 1, part = tid & 1;
    const uint32_t* qp =
        (const uint32_t*)(qkv + base + (size_t)row * (3 * kH) + h * kDH) +
        part * 16;
    const uint32_t* kp = qp + kH / 2;
    uint32_t* qd = Qs + row * kQStr + part * 16;
    uint32_t* kd = Ks + row * kQStr + part * 16;
#pragma unroll
    for (int i = 0; i < 4; ++i) {
      ((uint4*)qd)[i] = ((const uint4*)qp)[i];
      ((uint4*)kd)[i] = ((const uint4*)kp)[i];
    }
    const uint4* vp = (const uint4*)(qkv + base + (size_t)row * (3 * kH) +
                                     2 * kH + h * kDH + part * 32);
    __nv_bfloat16* vtb = (__nv_bfloat16*)Vt;
#pragma unroll
    for (int j = 0; j < 4; ++j) {
      uint4 v = vp[j];
      int d = part * 32 + j * 8;
      __nv_bfloat162 p0 = *(__nv_bfloat162*)&v.x;
      __nv_bfloat162 p1 = *(__nv_bfloat162*)&v.y;
      __nv_bfloat162 p2 = *(__nv_bfloat162*)&v.z;
      __nv_bfloat162 p3 = *(__nv_bfloat162*)&v.w;
      vtb[(d + 0) * (2 * kVStr) + row] = p0.x;
      vtb[(d + 1) * (2 * kVStr) + row] = p0.y;
      vtb[(d + 2) * (2 * kVStr) + row] = p1.x;
      vtb[(d + 3) * (2 * kVStr) + row] = p1.y;
      vtb[(d + 4) * (2 * kVStr) + row] = p2.x;
      vtb[(d + 5) * (2 * kVStr) + row] = p2.y;
      vtb[(d + 6) * (2 * kVStr) + row] = p3.x;
      vtb[(d + 7) * (2 * kVStr) + row] = p3.y;
    }
  }
  __syncthreads();

  float sacc[16][4];
#pragma unroll
  for (int nj = 0; nj < 16; ++nj)
#pragma unroll
    for (int c = 0; c < 4; ++c) sacc[nj][c] = 0.f;

  uint32_t a_base = (uint32_t)__cvta_generic_to_shared(
      Qs + (warp * 16 + (lane & 7) + ((lane >> 3) & 1) * 8) * kQStr +
      (lane >> 4) * 4);
  uint32_t k_base = (uint32_t)__cvta_generic_to_shared(
      Ks + ((lane & 7) + (lane >> 4) * 8) * kQStr + ((lane >> 3) & 1) * 4);

#pragma unroll
  for (int ks = 0; ks < 4; ++ks) {
    int kb = ks * 8;
    uint32_t af[4], bf[16][2];
    ldmatrix_x4(af[0], af[1], af[2], af[3], a_base + (uint32_t)(kb * 4));
#pragma unroll
    for (int p = 0; p < 8; ++p) {
      ldmatrix_x4(bf[p * 2][0], bf[p * 2][1], bf[p * 2 + 1][0],
                  bf[p * 2 + 1][1],
                  k_base + (uint32_t)((p * 16 * kQStr + kb) * 4));
    }
#pragma unroll
    for (int nj = 0; nj < 16; ++nj) mma_bf16(sacc[nj], af, bf[nj]);
  }

  const float scale = 0.125f;
  float mx0 = -1e30f, mx1 = -1e30f;
#pragma unroll
  for (int nj = 0; nj < 16; ++nj) {
    mx0 = fmaxf(mx0, fmaxf(sacc[nj][0], sacc[nj][1]));
    mx1 = fmaxf(mx1, fmaxf(sacc[nj][2], sacc[nj][3]));
  }
  mx0 = fmaxf(mx0, __shfl_xor_sync(~0u, mx0, 1));
  mx0 = fmaxf(mx0, __shfl_xor_sync(~0u, mx0, 2));
  mx1 = fmaxf(mx1, __shfl_xor_sync(~0u, mx1, 1));
  mx1 = fmaxf(mx1, __shfl_xor_sync(~0u, mx1, 2));
  mx0 *= scale;
  mx1 *= scale;
  float sum0 = 0.f, sum1 = 0.f;
#pragma unroll
  for (int nj = 0; nj < 16; ++nj) {
    sacc[nj][0] = __expf(sacc[nj][0] * scale - mx0);
    sacc[nj][1] = __expf(sacc[nj][1] * scale - mx0);
    sacc[nj][2] = __expf(sacc[nj][2] * scale - mx1);
    sacc[nj][3] = __expf(sacc[nj][3] * scale - mx1);
    sum0 += sacc[nj][0] + sacc[nj][1];
    sum1 += sacc[nj][2] + sacc[nj][3];
  }
  sum0 += __shfl_xor_sync(~0u, sum0, 1);
  sum0 += __shfl_xor_sync(~0u, sum0, 2);
  sum1 += __shfl_xor_sync(~0u, sum1, 1);
  sum1 += __shfl_xor_sync(~0u, sum1, 2);
  float inv0 = 1.f / sum0, inv1 = 1.f / sum1;

  uint32_t pfrag[8][4];
#pragma unroll
  for (int ks = 0; ks < 8; ++ks) {
    pfrag[ks][0] = pack_bf16(sacc[2 * ks][0] * inv0, sacc[2 * ks][1] * inv0);
    pfrag[ks][1] = pack_bf16(sacc[2 * ks][2] * inv1, sacc[2 * ks][3] * inv1);
    pfrag[ks][2] =
        pack_bf16(sacc[2 * ks + 1][0] * inv0, sacc[2 * ks + 1][1] * inv0);
    pfrag[ks][3] =
        pack_bf16(sacc[2 * ks + 1][2] * inv1, sacc[2 * ks + 1][3] * inv1);
  }

  float oacc[8][4];
#pragma unroll
  for (int nj = 0; nj < 8; ++nj)
#pragma unroll
    for (int c = 0; c < 4; ++c) oacc[nj][c] = 0.f;

  uint32_t v_base = (uint32_t)__cvta_generic_to_shared(
      Vt + ((lane & 7) + (lane >> 4) * 8) * kVStr + ((lane >> 3) & 1) * 4);
#pragma unroll
  for (int ks = 0; ks < 8; ++ks) {
    int kb = ks * 8;
    uint32_t bf[8][2];
#pragma unroll
    for (int p = 0; p < 4; ++p) {
      ldmatrix_x4(bf[p * 2][0], bf[p * 2][1], bf[p * 2 + 1][0],
                  bf[p * 2 + 1][1],
                  v_base + (uint32_t)((p * 16 * kVStr + kb) * 4));
    }
#pragma unroll
    for (int nj = 0; nj < 8; ++nj) mma_bf16(oacc[nj], pfrag[ks], bf[nj]);
  }

  int r0 = warp * 16 + g, r1 = r0 + 8;
  __nv_bfloat16* op = out + (size_t)(t * kN) * kH + h * kDH;
#pragma unroll
  for (int nj = 0; nj < 8; ++nj) {
    int col = nj * 8 + tg * 2;
    *(uint32_t*)(op + (size_t)r0 * kH + col) =
        pack_bf16(oacc[nj][0], oacc[nj][1]);
    *(uint32_t*)(op + (size_t)r1 * kH + col) =
        pack_bf16(oacc[nj][2], oacc[nj][3]);
  }
}

// ---------------------------------------------------------------------------
// LayerNorm: warp per token; writes fp32 x and bf16 xb.
// ---------------------------------------------------------------------------
__global__ __launch_bounds__(256) void ln_kernel(
    const float* __restrict__ y, const float* __restrict__ w,
    const float* __restrict__ b, float* __restrict__ x,
    __nv_bfloat16* __restrict__ xb) {
  int warp = threadIdx.x >> 5, lane = threadIdx.x & 31;
  size_t tok = (size_t)blockIdx.x * 8 + warp;
  const float* yp = y + tok * kH;
  float4 a = *(const float4*)(yp + lane * 4);
  float4 c = *(const float4*)(yp + 128 + lane * 4);
  float sum = a.x + a.y + a.z + a.w + c.x + c.y + c.z + c.w;
#pragma unroll
  for (int s = 16; s; s >>= 1) sum += __shfl_xor_sync(~0u, sum, s);
  float mu = sum * (1.f / kH);
  float d0 = a.x - mu, d1 = a.y - mu, d2 = a.z - mu, d3 = a.w - mu;
  float d4 = c.x - mu, d5 = c.y - mu, d6 = c.z - mu, d7 = c.w - mu;
  float sq = d0 * d0 + d1 * d1 + d2 * d2 + d3 * d3 + d4 * d4 + d5 * d5 +
             d6 * d6 + d7 * d7;
#pragma unroll
  for (int s = 16; s; s >>= 1) sq += __shfl_xor_sync(~0u, sq, s);
  float inv = rsqrtf(sq * (1.f / kH) + 1e-5f);
  float4 w0 = *(const float4*)(w + lane * 4);
  float4 w1 = *(const float4*)(w + 128 + lane * 4);
  float4 b0 = *(const float4*)(b + lane * 4);
  float4 b1 = *(const float4*)(b + 128 + lane * 4);
  float* xp = x + tok * kH;
  float4 o0 = {d0 * inv * w0.x + b0.x, d1 * inv * w0.y + b0.y,
               d2 * inv * w0.z + b0.z, d3 * inv * w0.w + b0.w};
  float4 o1 = {d4 * inv * w1.x + b1.x, d5 * inv * w1.y + b1.y,
               d6 * inv * w1.z + b1.z, d7 * inv * w1.w + b1.w};
  *(float4*)(xp + lane * 4) = o0;
  *(float4*)(xp + 128 + lane * 4) = o1;
  uint2 p0 = {pack_bf16(o0.x, o0.y), pack_bf16(o0.z, o0.w)};
  uint2 p1 = {pack_bf16(o1.x, o1.y), pack_bf16(o1.z, o1.w)};
  *(uint2*)(xb + tok * kH + lane * 4) = p0;
  *(uint2*)(xb + tok * kH + 128 + lane * 4) = p1;
}

// ---------------------------------------------------------------------------
// Output GEMM: out_pre[512,64] = x[512, 32768] @ W_out[64,32768]^T, split-K
// ---------------------------------------------------------------------------
constexpr int kKTotal = kN * kH;
constexpr int kKSplit = 16;
constexpr int kKChunk = kKTotal / kKSplit;

__global__ void zero_outpre() {
  int i = blockIdx.x * blockDim.x + threadIdx.x;
  if (i < kT * kOut) g_outpre[i] = 0.f;
}

__global__ void gemm_out_kernel(const float* __restrict__ Afull,
                                const float* __restrict__ Wout) {
  __shared__ float As[16][68];
  __shared__ float Bs[16][68];
  int m0 = blockIdx.y * 64;
  int kc0 = blockIdx.x * kKChunk;
  int tid = threadIdx.x;
  int tx = tid & 15, ty = tid >> 4;
  int lm = tid >> 2, lk = (tid & 3) * 4;
  float acc[4][4] = {};
  const float* Aptr = Afull + (size_t)(m0 + lm) * kKTotal + kc0 + lk;
  const float* Wptr = Wout + (size_t)lm * kKTotal + kc0 + lk;
  for (int k0 = 0; k0 < kKChunk; k0 += 16) {
    float4 av = *(const float4*)(Aptr + k0);
    float4 wv = *(const float4*)(Wptr + k0);
    As[lk + 0][lm] = av.x;
    As[lk + 1][lm] = av.y;
    As[lk + 2][lm] = av.z;
    As[lk + 3][lm] = av.w;
    Bs[lk + 0][lm] = wv.x;
    Bs[lk + 1][lm] = wv.y;
    Bs[lk + 2][lm] = wv.z;
    Bs[lk + 3][lm] = wv.w;
    __syncthreads();
#pragma unroll
    for (int k = 0; k < 16; ++k) {
      float4 a4 = *(const float4*)&As[k][ty * 4];
      float4 b4 = *(const float4*)&Bs[k][tx * 4];
      float a[4] = {a4.x, a4.y, a4.z, a4.w};
      float b[4] = {b4.x, b4.y, b4.z, b4.w};
#pragma unroll
      for (int i = 0; i < 4; ++i)
#pragma unroll
        for (int j = 0; j < 4; ++j) acc[i][j] += a[i] * b[j];
    }
    __syncthreads();
  }
#pragma unroll
  for (int i = 0; i < 4; ++i)
#pragma unroll
    for (int j = 0; j < 4; ++j)
      atomicAdd(&g_outpre[(m0 + ty * 4 + i) * kOut + tx * 4 + j], acc[i][j]);
}

__global__ void lnf_kernel(const float* __restrict__ b_out,
                           const float* __restrict__ w,
                           const float* __restrict__ bb,
                           float* __restrict__ out) {
  __shared__ float red[64];
  int t = blockIdx.x, o = threadIdx.x;
  float v = g_outpre[t * kOut + o] + b_out[o];
  red[o] = v;
  __syncthreads();
  for (int s = 32; s > 0; s >>= 1) {
    if (o < s) red[o] += red[o + s];
    __syncthreads();
  }
  float mu = red[0] * (1.f / kOut);
  __syncthreads();
  float d = v - mu;
  red[o] = d * d;
  __syncthreads();
  for (int s = 32; s > 0; s >>= 1) {
    if (o < s) red[o] += red[o + s];
    __syncthreads();
  }
  float var = red[0] * (1.f / kOut);
  out[t * kOut + o] = d * rsqrtf(var + 1e-5f) * w[o] + bb[o];
}

}  // namespace

extern "C" void kernel_launch(void* const* d_in, const int* in_sizes, int n_in,
                              void* d_out, int out_size) {
  const float* forest = (const float*)d_in[0];
  const int* adj = (const int*)d_in[1];
  const int* no = (const int*)d_in[2];
  const float* W_in = (const float*)d_in[3];
  const float* b_in = (const float*)d_in[4];
  const float* W_pos = (const float*)d_in[5];
  const float* b_pos = (const float*)d_in[6];
  const float* qkv_w = (const float*)d_in[7];
  const float* qkv_b = (const float*)d_in[8];
  const float* outp_w = (const float*)d_in[9];
  const float* outp_b = (const float*)d_in[10];
  const float* ln1_w = (const float*)d_in[11];
  const float* ln1_b = (const float*)d_in[12];
  const float* ff1_w = (const float*)d_in[13];
  const float* ff1_b = (const float*)d_in[14];
  const float* ff2_w = (const float*)d_in[15];
  const float* ff2_b = (const float*)d_in[16];
  const float* ln2_w = (const float*)d_in[17];
  const float* ln2_b = (const float*)d_in[18];
  const float* W_out = (const float*)d_in[19];
  const float* b_out = (const float*)d_in[20];
  const float* lnf_w = (const float*)d_in[21];
  const float* lnf_b = (const float*)d_in[22];
  float* out = (float*)d_out;

  float *px, *py;
  __nv_bfloat16 *pxb, *pqkvb, *pattnb, *pffb, *pwbf;
  cudaGetSymbolAddress((void**)&px, g_x);
  cudaGetSymbolAddress((void**)&py, g_y);
  cudaGetSymbolAddress((void**)&pxb, g_xb);
  cudaGetSymbolAddress((void**)&pqkvb, g_qkvb);
  cudaGetSymbolAddress((void**)&pattnb, g_attnb);
  cudaGetSymbolAddress((void**)&pffb, g_ffb);
  cudaGetSymbolAddress((void**)&pwbf, g_wbf);

  cudaFuncSetAttribute(attn_tc, cudaFuncAttributeMaxDynamicSharedMemorySize,
                       kAttnSmem);
  cudaFuncSetAttribute(gemm_bf<EPI_QKV_BF>,
                       cudaFuncAttributeMaxDynamicSharedMemorySize,
                       kGemmDynSmem);
  cudaFuncSetAttribute(gemm_bf<EPI_RELU_BF>,
                       cudaFuncAttributeMaxDynamicSharedMemorySize,
                       kGemmDynSmem);
  cudaFuncSetAttribute(gemm_bf<EPI_RES_F32>,
                       cudaFuncAttributeMaxDynamicSharedMemorySize,
                       kGemmDynSmem);

  // launch 0
  prep_parent_kernel<<<(kTN + 255) / 256, 256>>>(adj);
  // launch 1 (maxno + wpos transpose + weight bf16 conversion)
  prep2_kernel<<<kT + 384 + kWTotal / 256, 256>>>(no, W_pos, qkv_w, outp_w,
                                                  ff1_w, ff2_w);
  // launch 2
  embed_kernel<<<kTN / 32, 256>>>(forest, no, W_in, b_in, b_pos);

  dim3 blk(256);
  for (int l = 0; l < kL; ++l) {
    // launch 3 on l==0: ncu profiles this (qkv GEMM).
    gemm_bf<EPI_QKV_BF>
        <<<dim3((3 * kH) / 128, kTN / 128), blk, kGemmDynSmem>>>(
            pxb, pwbf + kWOffQkv + (size_t)l * 3 * kH * kH,
            qkv_b + (size_t)l * 3 * kH, nullptr, nullptr, pqkvb, kTN, 3 * kH,
            kH);
    attn_tc<<<kT * kHeads, 256, kAttnSmem>>>(pqkvb, pattnb);
    gemm_bf<EPI_RES_F32><<<dim3(kH / 128, kTN / 128), blk, kGemmDynSmem>>>(
        pattnb, pwbf + kWOffOutp + (size_t)l * kH * kH,
        outp_b + (size_t)l * kH, px, py, nullptr, kTN, kH, kH);
    ln_kernel<<<kTN / 8, 256>>>(py, ln1_w + (size_t)l * kH,
                                ln1_b + (size_t)l * kH, px, pxb);
    gemm_bf<EPI_RELU_BF><<<dim3(kFF / 128, kTN / 128), blk, kGemmDynSmem>>>(
        pxb, pwbf + kWOffFf1 + (size_t)l * kFF * kH, ff1_b + (size_t)l * kFF,
        nullptr, nullptr, pffb, kTN, kFF, kH);
    gemm_bf<EPI_RES_F32><<<dim3(kH / 128, kTN / 128), blk, kGemmDynSmem>>>(
        pffb, pwbf + kWOffFf2 + (size_t)l * kH * kFF, ff2_b + (size_t)l * kH,
        px, py, nullptr, kTN, kH, kFF);
    ln_kernel<<<kTN / 8, 256>>>(py, ln2_w + (size_t)l * kH,
                                ln2_b + (size_t)l * kH, px, pxb);
  }

  zero_outpre<<<(kT * kOut + 255) / 256, 256>>>();
  gemm_out_kernel<<<dim3(kKSplit, kT / 64), blk>>>(px, W_out);
  lnf_kernel<<<kT, kOut>>>(b_out, lnf_w, lnf_b, out);
}

// round 17
// speedup vs baseline: 1.4971x; 1.0087x over previous
#include <cuda_runtime.h>
#include <cuda_bf16.h>
#include <math.h>
#include <stdint.h>

namespace {

constexpr int kN = 128, kF = 16, kH = 256, kHeads = 4, kFF = 512,
              kOut = 64, kBF = 3, kL = 2, kP = 384, kT = 512, kE = 127,
              kDH = 64, kTN = kT * kN;

// ---- static device scratch (allocation-free) ----
__device__ float g_x[kTN * kH];                     // fp32 residual/LN state
__device__ float g_y[kTN * kH];                     // fp32 pre-LN temp
__device__ __nv_bfloat16 g_xb[kTN * kH];            // bf16 copy of x (GEMM A)
__device__ __nv_bfloat16 g_qkvb[kTN * 3 * kH];      // bf16 qkv
__device__ __nv_bfloat16 g_attnb[kTN * kH];         // bf16 attention out
__device__ __nv_bfloat16 g_ffb[kTN * kFF];          // bf16 ff1 out
__device__ __nv_bfloat16 g_wbf[1048576];            // layer weights, bf16
__device__ float g_outpre[kT * kOut];
__device__ float g_WposT[kP * kH];
__device__ int g_parent[kTN];
__device__ int g_slot[kTN];
__device__ int g_maxno[kT];

constexpr int kWOffQkv = 0;
constexpr int kWOffOutp = 393216;
constexpr int kWOffFf1 = 524288;
constexpr int kWOffFf2 = 786432;
constexpr int kWTotal = 1048576;

// ---------------------------------------------------------------------------
// Prep 1: parent/slot for every node + zero g_outpre (fused).
// ---------------------------------------------------------------------------
__global__ void prep_parent_kernel(const int* __restrict__ adj) {
  int i = blockIdx.x * blockDim.x + threadIdx.x;
  if (i >= kTN) return;
  if (i < kT * kOut) g_outpre[i] = 0.f;
  int local = i & (kN - 1);
  int tree = i >> 7;
  int par = -1, sl = 0;
  if (local != 0) {
    int e = tree * kE + local - 1;
    int p = adj[3 * e], c = adj[3 * e + 1], s = adj[3 * e + 2];
    if (c == i && p >= 0) {
      par = p;
      sl = s;
    }
  }
  g_parent[i] = par;
  g_slot[i] = sl;
}

// ---------------------------------------------------------------------------
// Prep 2: per-tree max(node_order) + W_pos transpose + weight bf16 convert.
// ---------------------------------------------------------------------------
__global__ void prep2_kernel(const int* __restrict__ no,
                             const float* __restrict__ W_pos,
                             const float* __restrict__ qkv_w,
                             const float* __restrict__ outp_w,
                             const float* __restrict__ ff1_w,
                             const float* __restrict__ ff2_w) {
  if (blockIdx.x < kT) {
    __shared__ int red[128];
    int t = blockIdx.x;
    if (threadIdx.x < 128) red[threadIdx.x] = no[t * kN + threadIdx.x];
    __syncthreads();
    for (int s = 64; s > 0; s >>= 1) {
      if (threadIdx.x < s)
        red[threadIdx.x] = max(red[threadIdx.x], red[threadIdx.x + s]);
      __syncthreads();
    }
    if (threadIdx.x == 0) g_maxno[t] = red[0];
  } else if (blockIdx.x < kT + 384) {
    int i = (blockIdx.x - kT) * blockDim.x + threadIdx.x;
    if (i < kP * kH) {
      int p = i / kH, h = i % kH;
      g_WposT[p * kH + h] = W_pos[h * kP + p];
    }
  } else {
    int i = (blockIdx.x - kT - 384) * blockDim.x + threadIdx.x;
    if (i < kWTotal) {
      float v;
      if (i < kWOffOutp) v = qkv_w[i];
      else if (i < kWOffFf1) v = outp_w[i - kWOffOutp];
      else if (i < kWOffFf2) v = ff1_w[i - kWOffFf1];
      else v = ff2_w[i - kWOffFf2];
      g_wbf[i] = __float2bfloat16(v);
    }
  }
}

// ---------------------------------------------------------------------------
// Embedding: writes fp32 x and bf16 xb.
// ---------------------------------------------------------------------------
__global__ void embed_kernel(const float* __restrict__ forest,
                             const int* __restrict__ no,
                             const float* __restrict__ W_in,
                             const float* __restrict__ b_in,
                             const float* __restrict__ b_pos) {
  __shared__ float Wins[kF][kH];
  __shared__ float bib[kH];
  __shared__ float fs[32][kF];
  __shared__ int anc[32][8];
  __shared__ int cnt[32];
  int tid = threadIdx.x;
  int base = blockIdx.x * 32;
#pragma unroll
  for (int j = 0; j < kH * kF / 256; ++j) {
    int idx = tid + j * 256;
    int h = idx / kF, f = idx % kF;
    Wins[f][h] = W_in[idx];
  }
  bib[tid] = b_in[tid] + b_pos[tid];
  {
    int idx = tid;
    if (idx < 32 * kF) {
      int tk = idx / kF, f = idx % kF;
      fs[tk][f] = forest[(size_t)(base + tk) * kF + f];
    }
    idx = tid + 256;
    if (idx < 32 * kF) {
      int tk = idx / kF, f = idx % kF;
      fs[tk][f] = forest[(size_t)(base + tk) * kF + f];
    }
  }
  if (tid < 32) {
    int tok = base + tid;
    int tree = tok / kN;
    int mx = g_maxno[tree];
    int c = tok, n = 0;
    for (int it = 0; it < 8; ++it) {
      int p = g_parent[c];
      if (p < 0) break;
      int pd = mx - no[p];
      int s = g_slot[c] + 1;
      s = s < 0 ? 0 : (s > kBF - 1 ? kBF - 1 : s);
      int idx = pd * kBF + s;
      if (idx >= 0 && idx < kP) anc[tid][n++] = idx;
      c = p;
    }
    cnt[tid] = n;
  }
  __syncthreads();
  int h = tid;
  for (int tk = 0; tk < 32; ++tk) {
    float acc = bib[h];
#pragma unroll
    for (int f = 0; f < kF; ++f) acc += fs[tk][f] * Wins[f][h];
    int c = cnt[tk];
    for (int a = 0; a < c; ++a) acc += g_WposT[anc[tk][a] * kH + h];
    g_x[(size_t)(base + tk) * kH + h] = acc;
    g_xb[(size_t)(base + tk) * kH + h] = __float2bfloat16(acc);
  }
}

// ---------------------------------------------------------------------------
// mma / ldmatrix / cp.async helpers
// ---------------------------------------------------------------------------
enum { EPI_QKV_BF = 0, EPI_RELU_BF = 1, EPI_RES_F32 = 2 };

__device__ __forceinline__ uint32_t pack_bf16(float x, float y) {
  __nv_bfloat162 h = __floats2bfloat162_rn(x, y);
  return *reinterpret_cast<uint32_t*>(&h);
}

__device__ __forceinline__ void mma_bf16(float* c, const uint32_t* a,
                                         const uint32_t* b) {
  asm("mma.sync.aligned.m16n8k16.row.col.f32.bf16.bf16.f32 "
      "{%0,%1,%2,%3},{%4,%5,%6,%7},{%8,%9},{%0,%1,%2,%3};"
      : "+f"(c[0]), "+f"(c[1]), "+f"(c[2]), "+f"(c[3])
      : "r"(a[0]), "r"(a[1]), "r"(a[2]), "r"(a[3]), "r"(b[0]), "r"(b[1]));
}

__device__ __forceinline__ void ldmatrix_x4(uint32_t& r0, uint32_t& r1,
                                            uint32_t& r2, uint32_t& r3,
                                            uint32_t addr) {
  asm volatile(
      "ldmatrix.sync.aligned.m8n8.x4.shared.b16 {%0,%1,%2,%3}, [%4];"
      : "=r"(r0), "=r"(r1), "=r"(r2), "=r"(r3)
      : "r"(addr));
}

__device__ __forceinline__ void ldmatrix_x4_trans(uint32_t& r0, uint32_t& r1,
                                                  uint32_t& r2, uint32_t& r3,
                                                  uint32_t addr) {
  asm volatile(
      "ldmatrix.sync.aligned.m8n8.x4.trans.shared.b16 {%0,%1,%2,%3}, [%4];"
      : "=r"(r0), "=r"(r1), "=r"(r2), "=r"(r3)
      : "r"(addr));
}

__device__ __forceinline__ void cp_async16(uint32_t saddr, const void* gaddr) {
  asm volatile("cp.async.cg.shared.global [%0], [%1], 16;" ::"r"(saddr),
               "l"(gaddr));
}
#define CP_COMMIT asm volatile("cp.async.commit_group;" ::: "memory")
#define CP_WAIT1 asm volatile("cp.async.wait_group 1;" ::: "memory")

// ---------------------------------------------------------------------------
// bf16 GEMM (R14/R15, passing): 2 stages, two syncs/iter, issue AFTER
// compute, K-tile 64. Row stride 36 u32.
// ---------------------------------------------------------------------------
constexpr int kGRowU32 = 36;
constexpr int kGStage = 128 * kGRowU32 * 4;        // 18432 B
constexpr int kGemmDynSmem = 4 * kGStage;          // 73728 B

template <int EPI>
__global__ __launch_bounds__(256, 2) void gemm_bf(
    const __nv_bfloat16* __restrict__ A, const __nv_bfloat16* __restrict__ W,
    const float* __restrict__ bias, const float* __restrict__ res,
    float* __restrict__ C, __nv_bfloat16* __restrict__ Cb, int M, int Nd,
    int K) {
  extern __shared__ __align__(16) uint32_t dsm[];
  int tid = threadIdx.x;
  int lane = tid & 31, warp = tid >> 5;
  int g = lane >> 2, tg = lane & 3;
  int wm = (warp & 1) * 64;
  int wn = (warp >> 1) * 32;
  int m0 = blockIdx.y * 128, n0 = blockIdx.x * 128;

  uint32_t As0 = (uint32_t)__cvta_generic_to_shared(dsm);
  uint32_t Bs0 = As0 + 2 * kGStage;

  float acc[4][4][4];
#pragma unroll
  for (int i = 0; i < 4; ++i)
#pragma unroll
    for (int j = 0; j < 4; ++j)
#pragma unroll
      for (int c = 0; c < 4; ++c) acc[i][j][c] = 0.f;

  auto issue = [&](int s, int kc) {
    uint32_t sa = As0 + s * kGStage;
    uint32_t sb = Bs0 + s * kGStage;
#pragma unroll
    for (int p = 0; p < 4; ++p) {
      int ci = tid + 256 * p;
      int row = ci >> 3, cq = ci & 7;
      uint32_t so = (uint32_t)(row * 144 + cq * 16);
      cp_async16(sa + so, A + (size_t)(m0 + row) * K + kc * 64 + cq * 8);
      cp_async16(sb + so, W + (size_t)(n0 + row) * K + kc * 64 + cq * 8);
    }
  };

  int a_row = wm + (lane & 7) + ((lane >> 3) & 1) * 8;
  int a_col = (lane >> 4) * 4;
  uint32_t a_base = As0 + (uint32_t)((a_row * kGRowU32 + a_col) * 4);
  int b_row = wn + (lane & 7) + (lane >> 4) * 8;
  int b_col = ((lane >> 3) & 1) * 4;
  uint32_t b_base = Bs0 + (uint32_t)((b_row * kGRowU32 + b_col) * 4);

  const int nk = K >> 6;
  issue(0, 0);
  CP_COMMIT;
  issue(1, 1);
  CP_COMMIT;

  for (int c = 0; c < nk; ++c) {
    int b = c & 1;
    CP_WAIT1;
    __syncthreads();
    uint32_t ab = a_base + b * kGStage;
    uint32_t bb = b_base + b * kGStage;
#pragma unroll
    for (int ks = 0; ks < 4; ++ks) {
      int kb = ks * 8;
      uint32_t af[4][4], bf[4][2];
#pragma unroll
      for (int mi = 0; mi < 4; ++mi) {
        ldmatrix_x4(af[mi][0], af[mi][1], af[mi][2], af[mi][3],
                    ab + (uint32_t)((mi * 16 * kGRowU32 + kb) * 4));
      }
#pragma unroll
      for (int p = 0; p < 2; ++p) {
        ldmatrix_x4(bf[p * 2][0], bf[p * 2][1], bf[p * 2 + 1][0],
                    bf[p * 2 + 1][1],
                    bb + (uint32_t)((p * 16 * kGRowU32 + kb) * 4));
      }
#pragma unroll
      for (int mi = 0; mi < 4; ++mi)
#pragma unroll
        for (int nj = 0; nj < 4; ++nj) mma_bf16(acc[mi][nj], af[mi], bf[nj]);
    }
    __syncthreads();
    if (c + 2 < nk) issue(b, c + 2);
    CP_COMMIT;
  }

#pragma unroll
  for (int nj = 0; nj < 4; ++nj) {
    int col = n0 + wn + nj * 8 + tg * 2;
    float b0 = bias[col], b1 = bias[col + 1];
#pragma unroll
    for (int mi = 0; mi < 4; ++mi) {
      int row = m0 + wm + mi * 16 + g;
      float v00 = acc[mi][nj][0] + b0;
      float v01 = acc[mi][nj][1] + b1;
      float v10 = acc[mi][nj][2] + b0;
      float v11 = acc[mi][nj][3] + b1;
      if (EPI == EPI_RELU_BF) {
        v00 = fmaxf(v00, 0.f);
        v01 = fmaxf(v01, 0.f);
        v10 = fmaxf(v10, 0.f);
        v11 = fmaxf(v11, 0.f);
      }
      if (EPI == EPI_RES_F32) {
        float2 r0 = *(const float2*)(res + (size_t)row * Nd + col);
        float2 r1 = *(const float2*)(res + (size_t)(row + 8) * Nd + col);
        v00 += r0.x;
        v01 += r0.y;
        v10 += r1.x;
        v11 += r1.y;
        float2 o0 = {v00, v01}, o1 = {v10, v11};
        *(float2*)(C + (size_t)row * Nd + col) = o0;
        *(float2*)(C + (size_t)(row + 8) * Nd + col) = o1;
      } else {
        *(uint32_t*)(Cb + (size_t)row * Nd + col) = pack_bf16(v00, v01);
        *(uint32_t*)(Cb + (size_t)(row + 8) * Nd + col) = pack_bf16(v10, v11);
      }
    }
  }
}

// ---------------------------------------------------------------------------
// bf16 tensor-core attention. V stored row-major [key][dim] (same vectorized
// copy as Q/K); P@V B-fragments via ldmatrix.x4.trans.
// Smem: Qs/Ks/Vs each 128 rows x 36 u32 -> 55296 B.
// ---------------------------------------------------------------------------
constexpr int kQStr = 36;
constexpr int kAttnSmem = 3 * 128 * kQStr * 4;  // 55296

__global__ __launch_bounds__(256, 2) void attn_tc(
    const __nv_bfloat16* __restrict__ qkv, __nv_bfloat16* __restrict__ out) {
  extern __shared__ uint32_t sm[];
  uint32_t* Qs = sm;
  uint32_t* Ks = sm + 128 * kQStr;
  uint32_t* Vs = sm + 2 * 128 * kQStr;
  int t = blockIdx.x >> 2, h = blockIdx.x & 3;
  int tid = threadIdx.x, lane = tid & 31, warp = tid >> 5;
  int g = lane >> 2, tg = lane & 3;
  const size_t base = (size_t)t * kN * (3 * kH);

  // ---- load Q, K, V (all identical vectorized row copies) ----
  {
    int row = tid >> 1, part = tid & 1;
    const uint32_t* qp =
        (const uint32_t*)(qkv + base + (size_t)row * (3 * kH) + h * kDH) +
        part * 16;
    const uint32_t* kp = qp + kH / 2;
    const uint32_t* vp = qp + kH;
    uint32_t* qd = Qs + row * kQStr + part * 16;
    uint32_t* kd = Ks + row * kQStr + part * 16;
    uint32_t* vd = Vs + row * kQStr + part * 16;
#pragma unroll
    for (int i = 0; i < 4; ++i) {
      ((uint4*)qd)[i] = ((const uint4*)qp)[i];
      ((uint4*)kd)[i] = ((const uint4*)kp)[i];
      ((uint4*)vd)[i] = ((const uint4*)vp)[i];
    }
  }
  __syncthreads();

  // ---- S = Q @ K^T ----
  float sacc[16][4];
#pragma unroll
  for (int nj = 0; nj < 16; ++nj)
#pragma unroll
    for (int c = 0; c < 4; ++c) sacc[nj][c] = 0.f;

  uint32_t a_base = (uint32_t)__cvta_generic_to_shared(
      Qs + (warp * 16 + (lane & 7) + ((lane >> 3) & 1) * 8) * kQStr +
      (lane >> 4) * 4);
  uint32_t k_base = (uint32_t)__cvta_generic_to_shared(
      Ks + ((lane & 7) + (lane >> 4) * 8) * kQStr + ((lane >> 3) & 1) * 4);

#pragma unroll
  for (int ks = 0; ks < 4; ++ks) {
    int kb = ks * 8;
    uint32_t af[4], bf[16][2];
    ldmatrix_x4(af[0], af[1], af[2], af[3], a_base + (uint32_t)(kb * 4));
#pragma unroll
    for (int p = 0; p < 8; ++p) {
      ldmatrix_x4(bf[p * 2][0], bf[p * 2][1], bf[p * 2 + 1][0],
                  bf[p * 2 + 1][1],
                  k_base + (uint32_t)((p * 16 * kQStr + kb) * 4));
    }
#pragma unroll
    for (int nj = 0; nj < 16; ++nj) mma_bf16(sacc[nj], af, bf[nj]);
  }

  // ---- softmax (quad shuffles) ----
  const float scale = 0.125f;
  float mx0 = -1e30f, mx1 = -1e30f;
#pragma unroll
  for (int nj = 0; nj < 16; ++nj) {
    mx0 = fmaxf(mx0, fmaxf(sacc[nj][0], sacc[nj][1]));
    mx1 = fmaxf(mx1, fmaxf(sacc[nj][2], sacc[nj][3]));
  }
  mx0 = fmaxf(mx0, __shfl_xor_sync(~0u, mx0, 1));
  mx0 = fmaxf(mx0, __shfl_xor_sync(~0u, mx0, 2));
  mx1 = fmaxf(mx1, __shfl_xor_sync(~0u, mx1, 1));
  mx1 = fmaxf(mx1, __shfl_xor_sync(~0u, mx1, 2));
  mx0 *= scale;
  mx1 *= scale;
  float sum0 = 0.f, sum1 = 0.f;
#pragma unroll
  for (int nj = 0; nj < 16; ++nj) {
    sacc[nj][0] = __expf(sacc[nj][0] * scale - mx0);
    sacc[nj][1] = __expf(sacc[nj][1] * scale - mx0);
    sacc[nj][2] = __expf(sacc[nj][2] * scale - mx1);
    sacc[nj][3] = __expf(sacc[nj][3] * scale - mx1);
    sum0 += sacc[nj][0] + sacc[nj][1];
    sum1 += sacc[nj][2] + sacc[nj][3];
  }
  sum0 += __shfl_xor_sync(~0u, sum0, 1);
  sum0 += __shfl_xor_sync(~0u, sum0, 2);
  sum1 += __shfl_xor_sync(~0u, sum1, 1);
  sum1 += __shfl_xor_sync(~0u, sum1, 2);
  float inv0 = 1.f / sum0, inv1 = 1.f / sum1;

  uint32_t pfrag[8][4];
#pragma unroll
  for (int ks = 0; ks < 8; ++ks) {
    pfrag[ks][0] = pack_bf16(sacc[2 * ks][0] * inv0, sacc[2 * ks][1] * inv0);
    pfrag[ks][1] = pack_bf16(sacc[2 * ks][2] * inv1, sacc[2 * ks][3] * inv1);
    pfrag[ks][2] =
        pack_bf16(sacc[2 * ks + 1][0] * inv0, sacc[2 * ks + 1][1] * inv0);
    pfrag[ks][3] =
        pack_bf16(sacc[2 * ks + 1][2] * inv1, sacc[2 * ks + 1][3] * inv1);
  }

  // ---- O = P @ V (V row-major, trans ldmatrix B-fragments) ----
  float oacc[8][4];
#pragma unroll
  for (int nj = 0; nj < 8; ++nj)
#pragma unroll
    for (int c = 0; c < 4; ++c) oacc[nj][c] = 0.f;

  // lane address: key row = (lane&7) + ((lane>>3)&1)*8, dim = (lane>>4)*8
  uint32_t v_base = (uint32_t)__cvta_generic_to_shared(Vs) +
                    (uint32_t)(((lane & 7) + ((lane >> 3) & 1) * 8) * 144 +
                               (lane >> 4) * 16);
#pragma unroll
  for (int ks = 0; ks < 8; ++ks) {
    // 16 keys per k-step -> +ks*16 rows = ks*2304 bytes
    uint32_t vk = v_base + (uint32_t)(ks * 16 * 144);
    uint32_t bf[8][2];
#pragma unroll
    for (int p = 0; p < 4; ++p) {
      // 16 dims per p -> +p*32 bytes
      ldmatrix_x4_trans(bf[p * 2][0], bf[p * 2][1], bf[p * 2 + 1][0],
                        bf[p * 2 + 1][1], vk + (uint32_t)(p * 32));
    }
#pragma unroll
    for (int nj = 0; nj < 8; ++nj) mma_bf16(oacc[nj], pfrag[ks], bf[nj]);
  }

  int r0 = warp * 16 + g, r1 = r0 + 8;
  __nv_bfloat16* op = out + (size_t)(t * kN) * kH + h * kDH;
#pragma unroll
  for (int nj = 0; nj < 8; ++nj) {
    int col = nj * 8 + tg * 2;
    *(uint32_t*)(op + (size_t)r0 * kH + col) =
        pack_bf16(oacc[nj][0], oacc[nj][1]);
    *(uint32_t*)(op + (size_t)r1 * kH + col) =
        pack_bf16(oacc[nj][2], oacc[nj][3]);
  }
}

// ---------------------------------------------------------------------------
// LayerNorm: warp per token; writes fp32 x and bf16 xb.
// ---------------------------------------------------------------------------
__global__ __launch_bounds__(256) void ln_kernel(
    const float* __restrict__ y, const float* __restrict__ w,
    const float* __restrict__ b, float* __restrict__ x,
    __nv_bfloat16* __restrict__ xb) {
  int warp = threadIdx.x >> 5, lane = threadIdx.x & 31;
  size_t tok = (size_t)blockIdx.x * 8 + warp;
  const float* yp = y + tok * kH;
  float4 a = *(const float4*)(yp + lane * 4);
  float4 c = *(const float4*)(yp + 128 + lane * 4);
  float sum = a.x + a.y + a.z + a.w + c.x + c.y + c.z + c.w;
#pragma unroll
  for (int s = 16; s; s >>= 1) sum += __shfl_xor_sync(~0u, sum, s);
  float mu = sum * (1.f / kH);
  float d0 = a.x - mu, d1 = a.y - mu, d2 = a.z - mu, d3 = a.w - mu;
  float d4 = c.x - mu, d5 = c.y - mu, d6 = c.z - mu, d7 = c.w - mu;
  float sq = d0 * d0 + d1 * d1 + d2 * d2 + d3 * d3 + d4 * d4 + d5 * d5 +
             d6 * d6 + d7 * d7;
#pragma unroll
  for (int s = 16; s; s >>= 1) sq += __shfl_xor_sync(~0u, sq, s);
  float inv = rsqrtf(sq * (1.f / kH) + 1e-5f);
  float4 w0 = *(const float4*)(w + lane * 4);
  float4 w1 = *(const float4*)(w + 128 + lane * 4);
  float4 b0 = *(const float4*)(b + lane * 4);
  float4 b1 = *(const float4*)(b + 128 + lane * 4);
  float* xp = x + tok * kH;
  float4 o0 = {d0 * inv * w0.x + b0.x, d1 * inv * w0.y + b0.y,
               d2 * inv * w0.z + b0.z, d3 * inv * w0.w + b0.w};
  float4 o1 = {d4 * inv * w1.x + b1.x, d5 * inv * w1.y + b1.y,
               d6 * inv * w1.z + b1.z, d7 * inv * w1.w + b1.w};
  *(float4*)(xp + lane * 4) = o0;
  *(float4*)(xp + 128 + lane * 4) = o1;
  uint2 p0 = {pack_bf16(o0.x, o0.y), pack_bf16(o0.z, o0.w)};
  uint2 p1 = {pack_bf16(o1.x, o1.y), pack_bf16(o1.z, o1.w)};
  *(uint2*)(xb + tok * kH + lane * 4) = p0;
  *(uint2*)(xb + tok * kH + 128 + lane * 4) = p1;
}

// ---------------------------------------------------------------------------
// Output GEMM: fp32 scalar split-K (proven; long-K needs fp32 operands).
// ---------------------------------------------------------------------------
constexpr int kKTotal = kN * kH;
constexpr int kKSplit = 16;
constexpr int kKChunk = kKTotal / kKSplit;

__global__ void gemm_out_kernel(const float* __restrict__ Afull,
                                const float* __restrict__ Wout) {
  __shared__ float As[16][68];
  __shared__ float Bs[16][68];
  int m0 = blockIdx.y * 64;
  int kc0 = blockIdx.x * kKChunk;
  int tid = threadIdx.x;
  int tx = tid & 15, ty = tid >> 4;
  int lm = tid >> 2, lk = (tid & 3) * 4;
  float acc[4][4] = {};
  const float* Aptr = Afull + (size_t)(m0 + lm) * kKTotal + kc0 + lk;
  const float* Wptr = Wout + (size_t)lm * kKTotal + kc0 + lk;
  for (int k0 = 0; k0 < kKChunk; k0 += 16) {
    float4 av = *(const float4*)(Aptr + k0);
    float4 wv = *(const float4*)(Wptr + k0);
    As[lk + 0][lm] = av.x;
    As[lk + 1][lm] = av.y;
    As[lk + 2][lm] = av.z;
    As[lk + 3][lm] = av.w;
    Bs[lk + 0][lm] = wv.x;
    Bs[lk + 1][lm] = wv.y;
    Bs[lk + 2][lm] = wv.z;
    Bs[lk + 3][lm] = wv.w;
    __syncthreads();
#pragma unroll
    for (int k = 0; k < 16; ++k) {
      float4 a4 = *(const float4*)&As[k][ty * 4];
      float4 b4 = *(const float4*)&Bs[k][tx * 4];
      float a[4] = {a4.x, a4.y, a4.z, a4.w};
      float b[4] = {b4.x, b4.y, b4.z, b4.w};
#pragma unroll
      for (int i = 0; i < 4; ++i)
#pragma unroll
        for (int j = 0; j < 4; ++j) acc[i][j] += a[i] * b[j];
    }
    __syncthreads();
  }
#pragma unroll
  for (int i = 0; i < 4; ++i)
#pragma unroll
    for (int j = 0; j < 4; ++j)
      atomicAdd(&g_outpre[(m0 + ty * 4 + i) * kOut + tx * 4 + j], acc[i][j]);
}

__global__ void lnf_kernel(const float* __restrict__ b_out,
                           const float* __restrict__ w,
                           const float* __restrict__ bb,
                           float* __restrict__ out) {
  __shared__ float red[64];
  int t = blockIdx.x, o = threadIdx.x;
  float v = g_outpre[t * kOut + o] + b_out[o];
  red[o] = v;
  __syncthreads();
  for (int s = 32; s > 0; s >>= 1) {
    if (o < s) red[o] += red[o + s];
    __syncthreads();
  }
  float mu = red[0] * (1.f / kOut);
  __syncthreads();
  float d = v - mu;
  red[o] = d * d;
  __syncthreads();
  for (int s = 32; s > 0; s >>= 1) {
    if (o < s) red[o] += red[o + s];
    __syncthreads();
  }
  float var = red[0] * (1.f / kOut);
  out[t * kOut + o] = d * rsqrtf(var + 1e-5f) * w[o] + bb[o];
}

}  // namespace

extern "C" void kernel_launch(void* const* d_in, const int* in_sizes, int n_in,
                              void* d_out, int out_size) {
  const float* forest = (const float*)d_in[0];
  const int* adj = (const int*)d_in[1];
  const int* no = (const int*)d_in[2];
  const float* W_in = (const float*)d_in[3];
  const float* b_in = (const float*)d_in[4];
  const float* W_pos = (const float*)d_in[5];
  const float* b_pos = (const float*)d_in[6];
  const float* qkv_w = (const float*)d_in[7];
  const float* qkv_b = (const float*)d_in[8];
  const float* outp_w = (const float*)d_in[9];
  const float* outp_b = (const float*)d_in[10];
  const float* ln1_w = (const float*)d_in[11];
  const float* ln1_b = (const float*)d_in[12];
  const float* ff1_w = (const float*)d_in[13];
  const float* ff1_b = (const float*)d_in[14];
  const float* ff2_w = (const float*)d_in[15];
  const float* ff2_b = (const float*)d_in[16];
  const float* ln2_w = (const float*)d_in[17];
  const float* ln2_b = (const float*)d_in[18];
  const float* W_out = (const float*)d_in[19];
  const float* b_out = (const float*)d_in[20];
  const float* lnf_w = (const float*)d_in[21];
  const float* lnf_b = (const float*)d_in[22];
  float* out = (float*)d_out;

  float *px, *py;
  __nv_bfloat16 *pxb, *pqkvb, *pattnb, *pffb, *pwbf;
  cudaGetSymbolAddress((void**)&px, g_x);
  cudaGetSymbolAddress((void**)&py, g_y);
  cudaGetSymbolAddress((void**)&pxb, g_xb);
  cudaGetSymbolAddress((void**)&pqkvb, g_qkvb);
  cudaGetSymbolAddress((void**)&pattnb, g_attnb);
  cudaGetSymbolAddress((void**)&pffb, g_ffb);
  cudaGetSymbolAddress((void**)&pwbf, g_wbf);

  cudaFuncSetAttribute(attn_tc, cudaFuncAttributeMaxDynamicSharedMemorySize,
                       kAttnSmem);
  cudaFuncSetAttribute(gemm_bf<EPI_QKV_BF>,
                       cudaFuncAttributeMaxDynamicSharedMemorySize,
                       kGemmDynSmem);
  cudaFuncSetAttribute(gemm_bf<EPI_RELU_BF>,
                       cudaFuncAttributeMaxDynamicSharedMemorySize,
                       kGemmDynSmem);
  cudaFuncSetAttribute(gemm_bf<EPI_RES_F32>,
                       cudaFuncAttributeMaxDynamicSharedMemorySize,
                       kGemmDynSmem);

  // launch 0 (parent/slot + zero g_outpre fused)
  prep_parent_kernel<<<(kTN + 255) / 256, 256>>>(adj);
  // launch 1 (maxno + wpos transpose + weight bf16 conversion)
  prep2_kernel<<<kT + 384 + kWTotal / 256, 256>>>(no, W_pos, qkv_w, outp_w,
                                                  ff1_w, ff2_w);
  // launch 2
  embed_kernel<<<kTN / 32, 256>>>(forest, no, W_in, b_in, b_pos);

  dim3 blk(256);
  for (int l = 0; l < kL; ++l) {
    // launch 3 on l==0: ncu profiles this (qkv GEMM).
    gemm_bf<EPI_QKV_BF>
        <<<dim3((3 * kH) / 128, kTN / 128), blk, kGemmDynSmem>>>(
            pxb, pwbf + kWOffQkv + (size_t)l * 3 * kH * kH,
            qkv_b + (size_t)l * 3 * kH, nullptr, nullptr, pqkvb, kTN, 3 * kH,
            kH);
    attn_tc<<<kT * kHeads, 256, kAttnSmem>>>(pqkvb, pattnb);
    gemm_bf<EPI_RES_F32><<<dim3(kH / 128, kTN / 128), blk, kGemmDynSmem>>>(
        pattnb, pwbf + kWOffOutp + (size_t)l * kH * kH,
        outp_b + (size_t)l * kH, px, py, nullptr, kTN, kH, kH);
    ln_kernel<<<kTN / 8, 256>>>(py, ln1_w + (size_t)l * kH,
                                ln1_b + (size_t)l * kH, px, pxb);
    gemm_bf<EPI_RELU_BF><<<dim3(kFF / 128, kTN / 128), blk, kGemmDynSmem>>>(
        pxb, pwbf + kWOffFf1 + (size_t)l * kFF * kH, ff1_b + (size_t)l * kFF,
        nullptr, nullptr, pffb, kTN, kFF, kH);
    gemm_bf<EPI_RES_F32><<<dim3(kH / 128, kTN / 128), blk, kGemmDynSmem>>>(
        pffb, pwbf + kWOffFf2 + (size_t)l * kH * kFF, ff2_b + (size_t)l * kH,
        px, py, nullptr, kTN, kH, kFF);
    ln_kernel<<<kTN / 8, 256>>>(py, ln2_w + (size_t)l * kH,
                                ln2_b + (size_t)l * kH, px, pxb);
  }

  gemm_out_kernel<<<dim3(kKSplit, kT / 64), blk>>>(px, W_out);
  lnf_kernel<<<kT, kOut>>>(b_out, lnf_w, lnf_b, out);
}